// round 16
// baseline (speedup 1.0000x reference)
#include <cuda_runtime.h>
#include <cuda_fp16.h>
#include <math.h>
#include <stdint.h>

// ---------------- problem constants ----------------
#define NB 8
#define CC 256
#define NGROUPS 16
#define GSIZE 16
#define GN_EPS 1e-5f

#define TOTHW   16800
#define CLSBASE 0
#define REGBASE 2688000
#define CTRBASE 3225600

#define WELEM  (CC * CC * 9)
#define WOELEM (9 * 32 * 256)

#define TOTPT 67
#define XCAP2 36070000

// per-level compile-time tables
__constant__ int cH[3]    = {100, 50, 25};
__constant__ int cW[3]    = {128, 64, 32};
__constant__ int cLgW[3]  = {7, 6, 5};
__constant__ int cWp[3]   = {130, 66, 34};
__constant__ int cHpWp[3] = {13260, 3432, 918};
__constant__ int cHW[3]   = {12800, 3200, 800};
__constant__ int cPT[3]   = {50, 13, 4};
__constant__ int cSegA[3] = {0, 50, 63};
__constant__ int cPoff[3] = {0, 12800, 16000};
__constant__ unsigned long long cXpix[3] = {0ull, 106080ull, 133536ull};
__constant__ int cFsegA[3] = {0, 25600, 32000};      // featprep block offsets
__constant__ int cZsegA[3] = {0, 117760, 177152};    // zeropad element offsets

// scratch (device globals; zero-initialized, no runtime allocation)
__device__ __align__(16) __half g_XFH[XCAP2];
__device__ __align__(16) float g_Y[4][XCAP2];
__device__ __align__(16) __half g_WF[4 * WELEM];
__device__ __align__(16) __half g_WOF[2 * WOELEM];
__device__ float  g_ssv[2 * 3 * 2 * 2048];
__device__ float  g_shv[2 * 3 * 2 * 2048];
__device__ float2 g_part[32 * TOTPT * 8];

// ---------------- PTX helpers (arch-agnostic sm_80+) ----------------
__device__ __forceinline__ uint32_t smem_u32(const void* p) {
    uint32_t a;
    asm("{ .reg .u64 t; cvta.to.shared.u64 t, %1; cvt.u32.u64 %0, t; }"
        : "=r"(a) : "l"(p));
    return a;
}
__device__ __forceinline__ void ldsm_x4(uint32_t& r0, uint32_t& r1,
                                        uint32_t& r2, uint32_t& r3, uint32_t a) {
    asm volatile("ldmatrix.sync.aligned.m8n8.x4.shared.b16 {%0,%1,%2,%3}, [%4];"
        : "=r"(r0), "=r"(r1), "=r"(r2), "=r"(r3) : "r"(a));
}
__device__ __forceinline__ void mma_f16(float* d, const uint32_t* a,
                                        const uint32_t* b) {
    asm volatile("mma.sync.aligned.m16n8k16.row.col.f32.f16.f16.f32 "
        "{%0,%1,%2,%3}, {%4,%5,%6,%7}, {%8,%9}, {%0,%1,%2,%3};"
        : "+f"(d[0]), "+f"(d[1]), "+f"(d[2]), "+f"(d[3])
        : "r"(a[0]), "r"(a[1]), "r"(a[2]), "r"(a[3]), "r"(b[0]), "r"(b[1]));
}
__device__ __forceinline__ void cpa16(uint32_t d, const void* s) {
    asm volatile("cp.async.cg.shared.global [%0], [%1], 16;"
                 :: "r"(d), "l"(s) : "memory");
}
__device__ __forceinline__ void cpa16z(uint32_t d, const void* s, uint32_t src_sz) {
    asm volatile("cp.async.cg.shared.global [%0], [%1], 16, %2;"
                 :: "r"(d), "l"(s), "r"(src_sz) : "memory");
}
#define CPA_COMMIT() asm volatile("cp.async.commit_group;" ::: "memory")
#define CPA_WAIT0()  asm volatile("cp.async.wait_group 0;" ::: "memory")

__device__ __forceinline__ uint32_t pkh(__half a, __half b) {
    __half2 t = __halves2half2(a, b);
    return *reinterpret_cast<uint32_t*>(&t);
}

// ---- convM smem: A 2-stage + B halo DOUBLE-buffered (hi only) ----
#define PITCH 144
#define ASTG  18432
#define OB0   36864
#define OB1   111744                 // OB0 + 520*144
#define OSS   186624                 // OB1 + 520*144
#define OSH   187648
#define CM_DYN 188672

// ---- convO smem: A 2-stage + B halo double-buffered ----
#define ASTG_O 4608
#define OB0_O  9216
#define OB1_O  84096
#define OSS_O  158976
#define OSH_O  160000
#define CO_DYN 161024

// ============================================================
// wprep / woprep
// ============================================================
__global__ __launch_bounds__(256) void wprep(
    const float* __restrict__ clsw, const float* __restrict__ regw,
    __half* __restrict__ WF)
{
    int idx = blockIdx.x * 256 + threadIdx.x;
    if (idx >= 4 * WELEM) return;
    int layer = idx / WELEM;
    int r0 = idx - layer * WELEM;
    int tap = r0 / 65536;
    int r   = r0 - tap * 65536;
    int co  = r >> 8, ci = r & 255;
    const float* src = (layer < 2 ? clsw : regw) + (size_t)(layer & 1) * WELEM;
    WF[idx] = __float2half_rn(src[co * 2304 + ci * 9 + tap]);
}

__global__ __launch_bounds__(256) void woprep(
    const float* __restrict__ clsw, const float* __restrict__ regw,
    const float* __restrict__ ctrw, __half* __restrict__ WOF)
{
    int idx = blockIdx.x * 256 + threadIdx.x;
    if (idx >= 2 * WOELEM) return;
    int set = idx / WOELEM;
    int r   = idx - set * WOELEM;
    int tap = r / 8192;
    int r2  = r - tap * 8192;
    int row = r2 >> 8, ci = r2 & 255;
    float v = 0.0f;
    if (set == 0) {
        if (row < 20) v = clsw[(row * 256 + ci) * 9 + tap];
    } else {
        if (row < 4)       v = regw[(row * 256 + ci) * 9 + tap];
        else if (row == 4) v = ctrw[ci * 9 + tap];
    }
    WOF[idx] = __float2half_rn(v);
}

// ============================================================
// zeropadAll: all 3 levels in one launch (fp16 feature buffer borders)
// ============================================================
__global__ __launch_bounds__(256) void zeropadAll(__half* __restrict__ XH)
{
    int idx = blockIdx.x * 256 + threadIdx.x;
    if (idx >= 207360) return;
    int L = (idx >= cZsegA[2]) ? 2 : (idx >= cZsegA[1]) ? 1 : 0;
    int e = idx - cZsegA[L];
    int H = cH[L], W = cW[L], Wp = cWp[L], HpWp = cHpWp[L];
    int bc = 2 * Wp + 2 * H;
    int ch4 = e & 31;
    int r   = e >> 5;
    int n   = r / bc;
    int b   = r - n * bc;
    int py, px;
    if (b < Wp)           { py = 0;     px = b; }
    else if (b < 2 * Wp)  { py = H + 1; px = b - Wp; }
    else {
        int rr = b - 2 * Wp;
        py = 1 + (rr >> 1);
        px = (rr & 1) ? (W + 1) : 0;
    }
    uint4* buf = (uint4*)(XH + (size_t)cXpix[L] * 256);
    buf[((size_t)n * HpWp + (size_t)py * Wp + px) * 32 + ch4] =
        make_uint4(0u, 0u, 0u, 0u);
}

// ============================================================
// featprepAll: all 3 levels, NCHW fp32 -> padded NHWC fp16
// ============================================================
__global__ __launch_bounds__(1024) void featprepAll(
    const float* __restrict__ f0, const float* __restrict__ f1,
    const float* __restrict__ f2, __half* __restrict__ XHb)
{
    __shared__ float tile[32][33];
    int b = blockIdx.x;
    int L = (b >= cFsegA[2]) ? 2 : (b >= cFsegA[1]) ? 1 : 0;
    b -= cFsegA[L];
    int H = cH[L], W = cW[L], Wp = cWp[L], HpWp = cHpWp[L];
    int wd = W >> 5;
    int xt = b % wd;
    int rem = b / wd;
    int y = rem % H;
    int nz = rem / H;
    int n = nz >> 3, ct = nz & 7;
    const float* feat = (L == 0) ? f0 : (L == 1) ? f1 : f2;
    __half* XH = XHb + (size_t)cXpix[L] * 256;
    int tx = threadIdx.x, ty = threadIdx.y;

    tile[ty][tx] = feat[(((size_t)n * CC + ct * 32 + ty) * H + y) * W + xt * 32 + tx];
    __syncthreads();

    int c = ct * 32 + tx;
    int x = xt * 32 + ty;
    XH[((size_t)n * HpWp + (size_t)(y + 1) * Wp + (x + 1)) * CC + c] =
        __float2half_rn(tile[tx][ty]);
}

// ============================================================
// convM: warp-mma 3x3 conv, single-term fp16, software-pipelined:
// A double-buffered per chunk; B halo double-buffered per ci-chunk,
// next chunk's fill smeared over the 9 taps of the current chunk.
// L1 (inH != null): pure cp.async B fill. L2: LDG -> GN -> fp16 STS,
// loads issued before the tap's MMAs, stores after.
// grid (TOTPT, 1, 32). 512 threads = 16 warps (4m x 4n).
// ============================================================
__global__ __launch_bounds__(512) void convM(
    const __half* __restrict__ inH,
    const float4* __restrict__ inC, const float4* __restrict__ inR,
    const uint4* __restrict__ WFb, int layer,
    const float* __restrict__ clscb, const float* __restrict__ regcb,
    const float* __restrict__ ssv, const float* __restrict__ shv,
    float* __restrict__ outC, float* __restrict__ outR,
    float2* __restrict__ part)
{
    extern __shared__ char smem[];
    const uint32_t sb = smem_u32(smem);

    const int bx = blockIdx.x;
    const int L = (bx >= cSegA[2]) ? 2 : (bx >= cSegA[1]) ? 1 : 0;
    const int tile = bx - cSegA[L];
    const int H = cH[L], W = cW[L], Wp = cWp[L], lgW = cLgW[L];
    const int HW = cHW[L], HpWp = cHpWp[L];
    const size_t lvlpix = (size_t)cXpix[L];

    const int tid = threadIdx.x, wid = tid >> 5, lane = tid & 31;
    const int warp_m = wid >> 2, warp_n = wid & 3;
    const int p0 = tile * 256;
    const int z = blockIdx.z;
    const int tower = z >> 4, zz = z & 15;
    const int n = zz >> 1, co0 = (zz & 1) * 128;
    const size_t nbase = lvlpix + (size_t)n * HpWp;

    const float4* in = tower ? inR : inC;
    float* Y = tower ? outR : outC;
    const uint4* WFl = WFb + (size_t)(tower * 2 + layer) * (WELEM / 8);
    const float* bias = (tower ? regcb : clscb) + layer * CC;

    const int R  = 256 >> lgW;
    const int BR = (R + 2) * Wp;
    const int prow0 = p0 >> lgW;
    const int pstart = prow0 * Wp;

    float* sS = (float*)(smem + OSS);
    float* sHh = (float*)(smem + OSH);
    if (ssv && tid < 256) {
        int so = (L * 2 + tower) * 2048 + n * 256 + tid;
        sS[tid]  = ssv[so];
        sHh[tid] = shv[so];
    }
    __syncthreads();

    float acc[2][8][4];
#pragma unroll
    for (int mt = 0; mt < 2; mt++)
#pragma unroll
        for (int nt = 0; nt < 8; nt++)
#pragma unroll
            for (int i = 0; i < 4; i++) acc[mt][nt][i] = 0.0f;

    const int lrow = lane & 7;
    const int matr = (lane >> 3) & 1;
    const int matc = lane >> 4;

    int rnp[4];
#pragma unroll
    for (int np = 0; np < 4; np++)
        rnp[np] = warp_n * 64 + np * 16 + matc * 8 + lrow;

    // ---- prologue: full B fill for kc=0 into OB0, A chunk 0 ----
    if (inH) {
#pragma unroll 1
        for (int t = tid; t < BR * 8; t += 512) {
            int hr = t >> 3, v = t & 7;
            int gpix = pstart + hr;
            uint32_t ok = (gpix < HpWp) ? 16u : 0u;
            cpa16z(sb + OB0 + (uint32_t)(hr * PITCH + v * 16),
                   inH + (nbase + gpix) * 256 + (v << 3), ok);
        }
    } else {
        const int lim = BR * 16;
#pragma unroll 1
        for (int t0 = tid; t0 < lim; t0 += 2048) {
            float4 xa[4];
#pragma unroll
            for (int u = 0; u < 4; u++) {
                int t = t0 + u * 512;
                xa[u] = make_float4(0.f, 0.f, 0.f, 0.f);
                if (t < lim) {
                    int hr = t >> 4, v = t & 15;
                    int gpix = pstart + hr;
                    if (gpix < HpWp)
                        xa[u] = in[(size_t)(nbase + gpix) * 64 + v];
                }
            }
#pragma unroll
            for (int u = 0; u < 4; u++) {
                int t = t0 + u * 512;
                if (t >= lim) break;
                int hr = t >> 4, v = t & 15;
                float4 x = xa[u];
                int hd = hr / Wp;
                int gx = hr - hd * Wp;
                int gy = prow0 + hd;
                if (gy >= 1 && gy <= H && gx >= 1 && gx <= W) {
                    int c = (v << 2);
                    x.x = fmaxf(fmaf(x.x, sS[c+0], sHh[c+0]), 0.f);
                    x.y = fmaxf(fmaf(x.y, sS[c+1], sHh[c+1]), 0.f);
                    x.z = fmaxf(fmaf(x.z, sS[c+2], sHh[c+2]), 0.f);
                    x.w = fmaxf(fmaf(x.w, sS[c+3], sHh[c+3]), 0.f);
                } else {
                    x = make_float4(0.f, 0.f, 0.f, 0.f);
                }
                *reinterpret_cast<uint2*>(smem + OB0 + hr * PITCH + (v << 3)) =
                    make_uint2(pkh(__float2half_rn(x.x), __float2half_rn(x.y)),
                               pkh(__float2half_rn(x.z), __float2half_rn(x.w)));
            }
        }
    }
    // A chunk 0
#pragma unroll
    for (int t = tid; t < 1024; t += 512) {
        int row = t >> 3, v = t & 7;
        cpa16(sb + (uint32_t)(row * PITCH + v * 16),
              WFl + (size_t)(co0 + row) * 32 + v);
    }
    CPA_COMMIT();
    CPA_WAIT0();
    __syncthreads();

    // slice sizes for pipelined B fill
    const int SL_CPA = (BR * 8 + 8) / 9;
    const int SL_CMP = (BR * 16 + 8) / 9;

    int kc = 0, tap = 0;
    int nkc = 0, ntap = 1;     // chunk c+1 coordinates
#pragma unroll 1
    for (int c = 0; c < 36; c++) {
        const uint32_t sAH = sb + (uint32_t)((c & 1) * ASTG);
        const uint32_t sBH = sb + ((kc & 1) ? OB1 : OB0);
        const uint32_t nBb = sb + (((kc + 1) & 1) ? OB1 : OB0);

        // A prefetch chunk c+1
        if (c < 35) {
            const uint32_t abase = sb + (uint32_t)(((c + 1) & 1) * ASTG);
#pragma unroll
            for (int t = tid; t < 1024; t += 512) {
                int row = t >> 3, v = t & 7;
                cpa16(abase + (uint32_t)(row * PITCH + v * 16),
                      WFl + (size_t)ntap * 8192 + (size_t)(co0 + row) * 32 + nkc * 8 + v);
            }
        }

        // B slice for kc+1 (this tap's slice)
        const int kcn = kc + 1;
        float4 xa0, xa1;
        int bt0 = -1, bt1 = -1;
        if (kcn < 4) {
            if (inH) {
                int s0 = tap * SL_CPA;
                int s1 = s0 + SL_CPA; if (s1 > BR * 8) s1 = BR * 8;
                for (int t = s0 + tid; t < s1; t += 512) {
                    int hr = t >> 3, v = t & 7;
                    int gpix = pstart + hr;
                    uint32_t ok = (gpix < HpWp) ? 16u : 0u;
                    cpa16z(nBb + (uint32_t)(hr * PITCH + v * 16),
                           inH + (nbase + gpix) * 256 + (kcn << 6) + (v << 3), ok);
                }
            } else {
                int s0 = tap * SL_CMP;
                int s1 = s0 + SL_CMP; if (s1 > BR * 16) s1 = BR * 16;
                int t = s0 + tid;
                xa0 = make_float4(0.f, 0.f, 0.f, 0.f);
                xa1 = make_float4(0.f, 0.f, 0.f, 0.f);
                if (t < s1) {
                    bt0 = t;
                    int hr = t >> 4, v = t & 15;
                    int gpix = pstart + hr;
                    if (gpix < HpWp)
                        xa0 = in[(size_t)(nbase + gpix) * 64 + (kcn << 4) + v];
                }
                t += 512;
                if (t < s1) {
                    bt1 = t;
                    int hr = t >> 4, v = t & 15;
                    int gpix = pstart + hr;
                    if (gpix < HpWp)
                        xa1 = in[(size_t)(nbase + gpix) * 64 + (kcn << 4) + v];
                }
            }
        }
        CPA_COMMIT();

        // ---- MMA for (kc, tap) ----
        {
            const int ky = tap / 3, kx = tap - ky * 3;
            uint32_t bOff[4];
#pragma unroll
            for (int np = 0; np < 4; np++) {
                int r = rnp[np];
                int sr = ((r >> lgW) + ky) * Wp + (r & (W - 1)) + kx;
                bOff[np] = (uint32_t)(sr * PITCH);
            }
            const int m0 = warp_m * 32;
#pragma unroll
            for (int ks = 0; ks < 4; ks++) {
                uint32_t ah[2][4], bb[4][4];
#pragma unroll
                for (int mt = 0; mt < 2; mt++) {
                    uint32_t off = (uint32_t)((m0 + mt * 16 + matr * 8 + lrow) * PITCH
                                              + (ks * 16 + matc * 8) * 2);
                    ldsm_x4(ah[mt][0], ah[mt][1], ah[mt][2], ah[mt][3], sAH + off);
                }
                const uint32_t kb = (uint32_t)((ks * 16 + matr * 8) * 2);
#pragma unroll
                for (int np = 0; np < 4; np++)
                    ldsm_x4(bb[np][0], bb[np][1], bb[np][2], bb[np][3],
                            sBH + bOff[np] + kb);
#pragma unroll
                for (int mt = 0; mt < 2; mt++)
#pragma unroll
                    for (int np = 0; np < 4; np++) {
                        mma_f16(acc[mt][np * 2 + 0], ah[mt], &bb[np][0]);
                        mma_f16(acc[mt][np * 2 + 1], ah[mt], &bb[np][2]);
                    }
            }
        }

        // ---- L2: GN + convert + STS the prefetched B slice ----
        if (kcn < 4 && !inH) {
#pragma unroll
            for (int u = 0; u < 2; u++) {
                int t = u ? bt1 : bt0;
                if (t < 0) continue;
                float4 x = u ? xa1 : xa0;
                int hr = t >> 4, v = t & 15;
                int hd = hr / Wp;
                int gx = hr - hd * Wp;
                int gy = prow0 + hd;
                if (gy >= 1 && gy <= H && gx >= 1 && gx <= W) {
                    int cch = (kcn << 6) + (v << 2);
                    x.x = fmaxf(fmaf(x.x, sS[cch+0], sHh[cch+0]), 0.f);
                    x.y = fmaxf(fmaf(x.y, sS[cch+1], sHh[cch+1]), 0.f);
                    x.z = fmaxf(fmaf(x.z, sS[cch+2], sHh[cch+2]), 0.f);
                    x.w = fmaxf(fmaf(x.w, sS[cch+3], sHh[cch+3]), 0.f);
                } else {
                    x = make_float4(0.f, 0.f, 0.f, 0.f);
                }
                *reinterpret_cast<uint2*>(smem + (nBb - sb) + hr * PITCH + (v << 3)) =
                    make_uint2(pkh(__float2half_rn(x.x), __float2half_rn(x.y)),
                               pkh(__float2half_rn(x.z), __float2half_rn(x.w)));
            }
        }

        if (c < 35) CPA_WAIT0();
        __syncthreads();

        if (++tap == 9) { tap = 0; kc++; }
        if (++ntap == 9) { ntap = 0; nkc++; }
    }

    // ---- epilogue: bias, store fp32 padded NHWC, deterministic GN partials ----
    __shared__ float redS[16][2], redQ[16][2];
    const int qrow = lane >> 2, qcol = (lane & 3) * 2;
    float sg[2] = {0.0f, 0.0f}, qg[2] = {0.0f, 0.0f};

#pragma unroll
    for (int mt = 0; mt < 2; mt++) {
#pragma unroll
        for (int h8 = 0; h8 < 2; h8++) {
            const int col_ = co0 + warp_m * 32 + mt * 16 + qrow + h8 * 8;
            const float b = bias[col_];
#pragma unroll
            for (int nt = 0; nt < 8; nt++) {
#pragma unroll
                for (int cc2 = 0; cc2 < 2; cc2++) {
                    int p = p0 + warp_n * 64 + nt * 8 + qcol + cc2;
                    float v = acc[mt][nt][h8 * 2 + cc2] + b;
                    if (p < HW) {
                        int x = p & (W - 1), y = p >> lgW;
                        Y[(nbase + (size_t)(y + 1) * Wp + (x + 1)) * CC + col_] = v;
                        sg[mt] += v;
                        qg[mt] += v * v;
                    }
                }
            }
        }
    }
#pragma unroll
    for (int off = 16; off > 0; off >>= 1) {
#pragma unroll
        for (int mt = 0; mt < 2; mt++) {
            sg[mt] += __shfl_down_sync(0xffffffffu, sg[mt], off);
            qg[mt] += __shfl_down_sync(0xffffffffu, qg[mt], off);
        }
    }
    if (lane == 0) {
        redS[wid][0] = sg[0]; redS[wid][1] = sg[1];
        redQ[wid][0] = qg[0]; redQ[wid][1] = qg[1];
    }
    __syncthreads();
    if (tid < 8) {
        int wm = tid >> 1, mt = tid & 1;
        float S = 0.0f, Q = 0.0f;
#pragma unroll
        for (int wn = 0; wn < 4; wn++) {
            S += redS[wm * 4 + wn][mt];
            Q += redQ[wm * 4 + wn][mt];
        }
        size_t pidx = (size_t)z * TOTPT + bx;
        part[pidx * 8 + tid] = make_float2(S, Q);
    }
}

// ============================================================
// gn_finalize2
// ============================================================
__global__ __launch_bounds__(256) void gn_finalize2(
    const float2* __restrict__ part,
    const float* __restrict__ clsg, const float* __restrict__ clsbt,
    const float* __restrict__ regg, const float* __restrict__ regbt,
    float* __restrict__ oss, float* __restrict__ osh)
{
    const int b = blockIdx.x;
    const int L = b >> 8;
    const int r = b & 255;
    const int tower = r >> 7;
    const int rr = r & 127;
    const int n = rr >> 4, grp = rr & 15;
    const int half = grp >> 3, i = grp & 7;
    const int z = tower * 16 + n * 2 + half;
    const int seg = cSegA[L], PT = cPT[L];

    float S = 0.0f, Q = 0.0f;
    for (int t = threadIdx.x; t < PT; t += 256) {
        float2 p = part[(size_t)(z * TOTPT + seg + t) * 8 + i];
        S += p.x; Q += p.y;
    }
    __shared__ float sS[256], sQ[256];
    sS[threadIdx.x] = S; sQ[threadIdx.x] = Q;
    __syncthreads();
    for (int off = 128; off > 0; off >>= 1) {
        if (threadIdx.x < off) {
            sS[threadIdx.x] += sS[threadIdx.x + off];
            sQ[threadIdx.x] += sQ[threadIdx.x + off];
        }
        __syncthreads();
    }
    if (threadIdx.x < 16) {
        float cnt  = (float)(GSIZE * cHW[L]);
        float mean = sS[0] / cnt;
        float var  = sQ[0] / cnt - mean * mean;
        float rstd = rsqrtf(var + GN_EPS);
        int c = grp * 16 + threadIdx.x;
        float gam = tower ? regg[c] : clsg[c];
        float bet = tower ? regbt[c] : clsbt[c];
        float scale = rstd * gam;
        int so = (L * 2 + tower) * 2048 + n * 256 + c;
        oss[so] = scale;
        osh[so] = bet - mean * scale;
    }
}

// ============================================================
// convO: head convs, single-term, software-pipelined B fill.
// grid (TOTPT, 1, 16): z = n*2 + mode. 256 threads = 8 warps.
// ============================================================
__global__ __launch_bounds__(256) void convO(
    const float4* __restrict__ inC, const float4* __restrict__ inR,
    const uint4* __restrict__ WOFb,
    const float* __restrict__ ssv, const float* __restrict__ shv,
    const float* __restrict__ clsb, const float* __restrict__ regb,
    const float* __restrict__ ctrb, float* __restrict__ out)
{
    extern __shared__ char smem[];
    const uint32_t sb = smem_u32(smem);

    const int bx = blockIdx.x;
    const int L = (bx >= cSegA[2]) ? 2 : (bx >= cSegA[1]) ? 1 : 0;
    const int tile = bx - cSegA[L];
    const int H = cH[L], W = cW[L], Wp = cWp[L], lgW = cLgW[L];
    const int HW = cHW[L], HpWp = cHpWp[L];
    const int poff = cPoff[L];
    const size_t lvlpix = (size_t)cXpix[L];

    const int tid = threadIdx.x, wid = tid >> 5, lane = tid & 31;
    const int p0 = tile * 256;
    const int z = blockIdx.z;
    const int n = z >> 1, mode = z & 1;
    const size_t nbase = lvlpix + (size_t)n * HpWp;

    const float4* in = mode ? inR : inC;
    const uint4* WFl = WOFb + (size_t)mode * (WOELEM / 8);

    const int R  = 256 >> lgW;
    const int BR = (R + 2) * Wp;
    const int prow0 = p0 >> lgW;
    const int pstart = prow0 * Wp;

    float* sS = (float*)(smem + OSS_O);
    float* sHh = (float*)(smem + OSH_O);
    if (tid < 256) {
        int so = (L * 2 + mode) * 2048 + n * 256 + tid;
        sS[tid]  = ssv[so];
        sHh[tid] = shv[so];
    }
    __syncthreads();

    float acc[2][4][4];
#pragma unroll
    for (int mt = 0; mt < 2; mt++)
#pragma unroll
        for (int nt = 0; nt < 4; nt++)
#pragma unroll
            for (int i = 0; i < 4; i++) acc[mt][nt][i] = 0.0f;

    const int lrow = lane & 7;
    const int matr = (lane >> 3) & 1;
    const int matc = lane >> 4;

    int rnp[2];
#pragma unroll
    for (int np = 0; np < 2; np++)
        rnp[np] = wid * 32 + np * 16 + matc * 8 + lrow;

    // ---- prologue: full B fill for kc=0 into OB0_O, A chunk 0 ----
    {
        const int lim = BR * 16;
#pragma unroll 1
        for (int t0 = tid; t0 < lim; t0 += 1024) {
            float4 xa[4];
#pragma unroll
            for (int u = 0; u < 4; u++) {
                int t = t0 + u * 256;
                xa[u] = make_float4(0.f, 0.f, 0.f, 0.f);
                if (t < lim) {
                    int hr = t >> 4, v = t & 15;
                    int gpix = pstart + hr;
                    if (gpix < HpWp)
                        xa[u] = in[(size_t)(nbase + gpix) * 64 + v];
                }
            }
#pragma unroll
            for (int u = 0; u < 4; u++) {
                int t = t0 + u * 256;
                if (t >= lim) break;
                int hr = t >> 4, v = t & 15;
                float4 x = xa[u];
                int hd = hr / Wp;
                int gx = hr - hd * Wp;
                int gy = prow0 + hd;
                if (gy >= 1 && gy <= H && gx >= 1 && gx <= W) {
                    int c = (v << 2);
                    x.x = fmaxf(fmaf(x.x, sS[c+0], sHh[c+0]), 0.f);
                    x.y = fmaxf(fmaf(x.y, sS[c+1], sHh[c+1]), 0.f);
                    x.z = fmaxf(fmaf(x.z, sS[c+2], sHh[c+2]), 0.f);
                    x.w = fmaxf(fmaf(x.w, sS[c+3], sHh[c+3]), 0.f);
                } else {
                    x = make_float4(0.f, 0.f, 0.f, 0.f);
                }
                *reinterpret_cast<uint2*>(smem + OB0_O + hr * PITCH + (v << 3)) =
                    make_uint2(pkh(__float2half_rn(x.x), __float2half_rn(x.y)),
                               pkh(__float2half_rn(x.z), __float2half_rn(x.w)));
            }
        }
        int row = tid >> 3, v = tid & 7;
        cpa16(sb + (uint32_t)(row * PITCH + v * 16), WFl + (size_t)row * 32 + v);
    }
    CPA_COMMIT();
    CPA_WAIT0();
    __syncthreads();

    const int SL = (BR * 16 + 8) / 9;

    int kc = 0, tap = 0;
    int nkc = 0, ntap = 1;
#pragma unroll 1
    for (int c = 0; c < 36; c++) {
        const uint32_t sAH = sb + (uint32_t)((c & 1) * ASTG_O);
        const uint32_t sBH = sb + ((kc & 1) ? OB1_O : OB0_O);
        const uint32_t nBb = sb + (((kc + 1) & 1) ? OB1_O : OB0_O);

        if (c < 35) {
            const uint32_t abase = sb + (uint32_t)(((c + 1) & 1) * ASTG_O);
            int row = tid >> 3, v = tid & 7;
            cpa16(abase + (uint32_t)(row * PITCH + v * 16),
                  WFl + (size_t)ntap * 1024 + (size_t)row * 32 + nkc * 8 + v);
        }

        const int kcn = kc + 1;
        float4 xa[4];
        int bt[4] = {-1, -1, -1, -1};
        if (kcn < 4) {
            int s0 = tap * SL;
            int s1 = s0 + SL; if (s1 > BR * 16) s1 = BR * 16;
#pragma unroll
            for (int u = 0; u < 4; u++) {
                int t = s0 + tid + u * 256;
                xa[u] = make_float4(0.f, 0.f, 0.f, 0.f);
                if (t < s1) {
                    bt[u] = t;
                    int hr = t >> 4, v = t & 15;
                    int gpix = pstart + hr;
                    if (gpix < HpWp)
                        xa[u] = in[(size_t)(nbase + gpix) * 64 + (kcn << 4) + v];
                }
            }
        }
        CPA_COMMIT();

        // ---- MMA for (kc, tap) ----
        {
            const int ky = tap / 3, kx = tap - ky * 3;
            uint32_t bOff[2];
#pragma unroll
            for (int np = 0; np < 2; np++) {
                int r = rnp[np];
                int sr = ((r >> lgW) + ky) * Wp + (r & (W - 1)) + kx;
                bOff[np] = (uint32_t)(sr * PITCH);
            }
#pragma unroll
            for (int ks = 0; ks < 4; ks++) {
                uint32_t ah[2][4], bb[2][4];
#pragma unroll
                for (int mt = 0; mt < 2; mt++) {
                    uint32_t off = (uint32_t)((mt * 16 + matr * 8 + lrow) * PITCH
                                              + (ks * 16 + matc * 8) * 2);
                    ldsm_x4(ah[mt][0], ah[mt][1], ah[mt][2], ah[mt][3], sAH + off);
                }
                const uint32_t kb = (uint32_t)((ks * 16 + matr * 8) * 2);
#pragma unroll
                for (int np = 0; np < 2; np++)
                    ldsm_x4(bb[np][0], bb[np][1], bb[np][2], bb[np][3],
                            sBH + bOff[np] + kb);
#pragma unroll
                for (int mt = 0; mt < 2; mt++)
#pragma unroll
                    for (int np = 0; np < 2; np++) {
                        mma_f16(acc[mt][np * 2 + 0], ah[mt], &bb[np][0]);
                        mma_f16(acc[mt][np * 2 + 1], ah[mt], &bb[np][2]);
                    }
            }
        }

        if (kcn < 4) {
#pragma unroll
            for (int u = 0; u < 4; u++) {
                int t = bt[u];
                if (t < 0) continue;
                float4 x = xa[u];
                int hr = t >> 4, v = t & 15;
                int hd = hr / Wp;
                int gx = hr - hd * Wp;
                int gy = prow0 + hd;
                if (gy >= 1 && gy <= H && gx >= 1 && gx <= W) {
                    int cch = (kcn << 6) + (v << 2);
                    x.x = fmaxf(fmaf(x.x, sS[cch+0], sHh[cch+0]), 0.f);
                    x.y = fmaxf(fmaf(x.y, sS[cch+1], sHh[cch+1]), 0.f);
                    x.z = fmaxf(fmaf(x.z, sS[cch+2], sHh[cch+2]), 0.f);
                    x.w = fmaxf(fmaf(x.w, sS[cch+3], sHh[cch+3]), 0.f);
                } else {
                    x = make_float4(0.f, 0.f, 0.f, 0.f);
                }
                *reinterpret_cast<uint2*>(smem + (nBb - sb) + hr * PITCH + (v << 3)) =
                    make_uint2(pkh(__float2half_rn(x.x), __float2half_rn(x.y)),
                               pkh(__float2half_rn(x.z), __float2half_rn(x.w)));
            }
        }

        if (c < 35) CPA_WAIT0();
        __syncthreads();

        if (++tap == 9) { tap = 0; kc++; }
        if (++ntap == 9) { ntap = 0; nkc++; }
    }

    // ---- epilogue: scatter into concat output layout ----
    const int qrow = lane >> 2, qcol = (lane & 3) * 2;
#pragma unroll
    for (int mt = 0; mt < 2; mt++) {
#pragma unroll
        for (int h8 = 0; h8 < 2; h8++) {
            const int row = mt * 16 + h8 * 8 + qrow;
#pragma unroll
            for (int nt = 0; nt < 4; nt++) {
#pragma unroll
                for (int cc2 = 0; cc2 < 2; cc2++) {
                    int p = p0 + wid * 32 + nt * 8 + qcol + cc2;
                    if (p >= HW) continue;
                    float v = acc[mt][nt][h8 * 2 + cc2];
                    int x = p & (W - 1), y = p >> lgW;
                    size_t gp = (size_t)n * TOTHW + poff + (size_t)y * W + x;
                    if (mode == 0) {
                        if (row < 20) out[CLSBASE + gp * 20 + row] = v + clsb[row];
                    } else {
                        if (row < 4)
                            out[REGBASE + gp * 4 + row] = fmaxf(v + regb[row], 0.0f);
                        else if (row == 4)
                            out[CTRBASE + gp] = v + ctrb[0];
                    }
                }
            }
        }
    }
}

// ============================================================
// host launcher
// ============================================================
extern "C" void kernel_launch(void* const* d_in, const int* in_sizes, int n_in,
                              void* d_out, int out_size)
{
    (void)in_sizes; (void)n_in; (void)out_size;

    const float* feat[3] = { (const float*)d_in[0], (const float*)d_in[1],
                             (const float*)d_in[2] };
    const float* cls_conv_w = (const float*)d_in[3];
    const float* cls_conv_b = (const float*)d_in[4];
    const float* cls_gn_g   = (const float*)d_in[5];
    const float* cls_gn_b   = (const float*)d_in[6];
    const float* cls_out_w  = (const float*)d_in[7];
    const float* cls_out_b  = (const float*)d_in[8];
    const float* reg_conv_w = (const float*)d_in[9];
    const float* reg_conv_b = (const float*)d_in[10];
    const float* reg_gn_g   = (const float*)d_in[11];
    const float* reg_gn_b   = (const float*)d_in[12];
    const float* reg_out_w  = (const float*)d_in[13];
    const float* reg_out_b  = (const float*)d_in[14];
    const float* ctr_w      = (const float*)d_in[15];
    const float* ctr_b      = (const float*)d_in[16];

    float* out = (float*)d_out;

    __half *XFH, *WF, *WOF;
    float *Y0, *Y1, *Y2, *Y3, *ssv, *shv;
    float2* part;
    cudaGetSymbolAddress((void**)&XFH, g_XFH);
    {
        float* ybase;
        cudaGetSymbolAddress((void**)&ybase, g_Y);
        Y0 = ybase;
        Y1 = ybase + (size_t)XCAP2;
        Y2 = ybase + 2 * (size_t)XCAP2;
        Y3 = ybase + 3 * (size_t)XCAP2;
    }
    cudaGetSymbolAddress((void**)&WF, g_WF);
    cudaGetSymbolAddress((void**)&WOF, g_WOF);
    cudaGetSymbolAddress((void**)&ssv, g_ssv);
    cudaGetSymbolAddress((void**)&shv, g_shv);
    cudaGetSymbolAddress((void**)&part, g_part);

    cudaFuncSetAttribute(convM, cudaFuncAttributeMaxDynamicSharedMemorySize, CM_DYN);
    cudaFuncSetAttribute(convO, cudaFuncAttributeMaxDynamicSharedMemorySize, CO_DYN);

    wprep<<<(4 * WELEM + 255) / 256, 256>>>(cls_conv_w, reg_conv_w, WF);
    woprep<<<(2 * WOELEM + 255) / 256, 256>>>(cls_out_w, reg_out_w, ctr_w, WOF);

    zeropadAll<<<(207360 + 255) / 256, 256>>>(XFH);
    featprepAll<<<33600, dim3(32, 32)>>>(feat[0], feat[1], feat[2], XFH);

    dim3 cgrid(TOTPT, 1, 32);
    dim3 ogrid(TOTPT, 1, 16);

    // conv layer 1: fp16 feature input, pipelined cp.async B fill
    convM<<<cgrid, 512, CM_DYN>>>(
        XFH, nullptr, nullptr,
        (const uint4*)WF, 0,
        cls_conv_b, reg_conv_b, nullptr, nullptr,
        Y0, Y1, part);
    gn_finalize2<<<768, 256>>>(part,
        cls_gn_g, cls_gn_b, reg_gn_g, reg_gn_b, ssv, shv);

    // conv layer 2: fp32 Y input, pipelined compute B fill + fused GN
    convM<<<cgrid, 512, CM_DYN>>>(
        nullptr, (const float4*)Y0, (const float4*)Y1,
        (const uint4*)WF, 1,
        cls_conv_b, reg_conv_b, ssv, shv,
        Y2, Y3, part);
    gn_finalize2<<<768, 256>>>(part,
        cls_gn_g + CC, cls_gn_b + CC, reg_gn_g + CC, reg_gn_b + CC,
        ssv + 12288, shv + 12288);

    // heads (single-term), pipelined fill, GN of layer 2 fused on load
    convO<<<ogrid, 256, CO_DYN>>>(
        (const float4*)Y2, (const float4*)Y3,
        (const uint4*)WOF,
        ssv + 12288, shv + 12288,
        cls_out_b, reg_out_b, ctr_b, out);
}

// round 17
// speedup vs baseline: 1.1920x; 1.1920x over previous
#include <cuda_runtime.h>
#include <cuda_fp16.h>
#include <math.h>
#include <stdint.h>

// ---------------- problem constants ----------------
#define NB 8
#define CC 256
#define NGROUPS 16
#define GSIZE 16
#define GN_EPS 1e-5f

#define TOTHW   16800
#define CLSBASE 0
#define REGBASE 2688000
#define CTRBASE 3225600

#define WELEM  (CC * CC * 9)      // 589824 fp16 per tower layer
#define WOELEM (9 * 32 * 256)     // 73728 per head set

#define TOTPT 67                  // 50 + 13 + 4 px-tiles across levels
#define XCAP2 36070000            // all-level padded NHWC capacity

// per-level compile-time tables
__constant__ int cH[3]    = {100, 50, 25};
__constant__ int cW[3]    = {128, 64, 32};
__constant__ int cLgW[3]  = {7, 6, 5};
__constant__ int cWp[3]   = {130, 66, 34};
__constant__ int cHpWp[3] = {13260, 3432, 918};
__constant__ int cHW[3]   = {12800, 3200, 800};
__constant__ int cPT[3]   = {50, 13, 4};
__constant__ int cSegA[3] = {0, 50, 63};
__constant__ int cPoff[3] = {0, 12800, 16000};
__constant__ unsigned long long cXpix[3] = {0ull, 106080ull, 133536ull};

// scratch (device globals; zero-initialized, no runtime allocation)
__device__ __align__(16) __half g_XFH[XCAP2];         // features fp16 padded NHWC
__device__ __align__(16) float g_Y[4][XCAP2];         // tower outputs fp32
__device__ __align__(16) __half g_WF[4 * WELEM];
__device__ __align__(16) __half g_WOF[2 * WOELEM];
__device__ float  g_ssv[2 * 3 * 2 * 2048];   // [conv][level][tower][n*256+c]
__device__ float  g_shv[2 * 3 * 2 * 2048];
__device__ float2 g_part[32 * TOTPT * 8];

// ---------------- PTX helpers (arch-agnostic sm_80+) ----------------
__device__ __forceinline__ uint32_t smem_u32(const void* p) {
    uint32_t a;
    asm("{ .reg .u64 t; cvta.to.shared.u64 t, %1; cvt.u32.u64 %0, t; }"
        : "=r"(a) : "l"(p));
    return a;
}
__device__ __forceinline__ void ldsm_x4(uint32_t& r0, uint32_t& r1,
                                        uint32_t& r2, uint32_t& r3, uint32_t a) {
    asm volatile("ldmatrix.sync.aligned.m8n8.x4.shared.b16 {%0,%1,%2,%3}, [%4];"
        : "=r"(r0), "=r"(r1), "=r"(r2), "=r"(r3) : "r"(a));
}
__device__ __forceinline__ void mma_f16(float* d, const uint32_t* a,
                                        const uint32_t* b) {
    asm volatile("mma.sync.aligned.m16n8k16.row.col.f32.f16.f16.f32 "
        "{%0,%1,%2,%3}, {%4,%5,%6,%7}, {%8,%9}, {%0,%1,%2,%3};"
        : "+f"(d[0]), "+f"(d[1]), "+f"(d[2]), "+f"(d[3])
        : "r"(a[0]), "r"(a[1]), "r"(a[2]), "r"(a[3]), "r"(b[0]), "r"(b[1]));
}
__device__ __forceinline__ void cpa16(uint32_t d, const void* s) {
    asm volatile("cp.async.cg.shared.global [%0], [%1], 16;"
                 :: "r"(d), "l"(s) : "memory");
}
// zero-fill variant: bytes beyond src_sz are written as 0
__device__ __forceinline__ void cpa16z(uint32_t d, const void* s, uint32_t src_sz) {
    asm volatile("cp.async.cg.shared.global [%0], [%1], 16, %2;"
                 :: "r"(d), "l"(s), "r"(src_sz) : "memory");
}
#define CPA_COMMIT() asm volatile("cp.async.commit_group;" ::: "memory")
#define CPA_WAIT0()  asm volatile("cp.async.wait_group 0;" ::: "memory")

__device__ __forceinline__ uint32_t pkh(__half a, __half b) {
    __half2 t = __halves2half2(a, b);
    return *reinterpret_cast<uint32_t*>(&t);
}

// ---- convM smem geometry (dynamic): A 2-stage + B halo (hi only) ----
#define PITCH 144
#define ASTG  18432
#define OB_H  36864
#define OSS   111744                 // OB_H + 520*144
#define OSH   112768
#define CM_DYN 113792

// ---- convO smem geometry (dynamic): B halo hi only ----
#define ASTG_O 4608
#define OB_H_O 9216
#define OSS_O  84096                 // OB_H_O + 520*144
#define OSH_O  85120
#define CO_DYN 86144

// ============================================================
// wprep: all 4 tower layers in one launch.
// ============================================================
__global__ __launch_bounds__(256) void wprep(
    const float* __restrict__ clsw, const float* __restrict__ regw,
    __half* __restrict__ WF)
{
    int idx = blockIdx.x * 256 + threadIdx.x;
    if (idx >= 4 * WELEM) return;
    int layer = idx / WELEM;
    int r0 = idx - layer * WELEM;
    int tap = r0 / 65536;
    int r   = r0 - tap * 65536;
    int co  = r >> 8, ci = r & 255;
    const float* src = (layer < 2 ? clsw : regw) + (size_t)(layer & 1) * WELEM;
    WF[idx] = __float2half_rn(src[co * 2304 + ci * 9 + tap]);
}

// ============================================================
// woprep: head weights -> [set][tap][row32][ci] fp16
// ============================================================
__global__ __launch_bounds__(256) void woprep(
    const float* __restrict__ clsw, const float* __restrict__ regw,
    const float* __restrict__ ctrw, __half* __restrict__ WOF)
{
    int idx = blockIdx.x * 256 + threadIdx.x;
    if (idx >= 2 * WOELEM) return;
    int set = idx / WOELEM;
    int r   = idx - set * WOELEM;
    int tap = r / 8192;
    int r2  = r - tap * 8192;
    int row = r2 >> 8, ci = r2 & 255;
    float v = 0.0f;
    if (set == 0) {
        if (row < 20) v = clsw[(row * 256 + ci) * 9 + tap];
    } else {
        if (row < 4)       v = regw[(row * 256 + ci) * 9 + tap];
        else if (row == 4) v = ctrw[ci * 9 + tap];
    }
    WOF[idx] = __float2half_rn(v);
}

// ============================================================
// zeropad_h: zero border pixels of one level's padded NHWC fp16 buffer
// ============================================================
__global__ __launch_bounds__(256) void zeropad_h(
    uint4* __restrict__ buf, int H, int W, int Wp, int HpWp)
{
    int bc = 2 * Wp + 2 * H;
    int total = NB * bc * 32;            // 256 half = 32 uint4 per pixel
    int idx = blockIdx.x * 256 + threadIdx.x;
    if (idx >= total) return;
    int ch4 = idx & 31;
    int r   = idx >> 5;
    int n   = r / bc;
    int b   = r - n * bc;
    int py, px;
    if (b < Wp)           { py = 0;     px = b; }
    else if (b < 2 * Wp)  { py = H + 1; px = b - Wp; }
    else {
        int rr = b - 2 * Wp;
        py = 1 + (rr >> 1);
        px = (rr & 1) ? (W + 1) : 0;
    }
    buf[((size_t)n * HpWp + (size_t)py * Wp + px) * 32 + ch4] =
        make_uint4(0u, 0u, 0u, 0u);
}

// ============================================================
// featprep4: NCHW fp32 -> padded NHWC fp16, 4 image rows per block.
// grid (W/32, ceil(H/4), NB*8), block (32,32).
// ============================================================
__global__ __launch_bounds__(1024) void featprep4(
    const float* __restrict__ feat, __half* __restrict__ XH,
    int H, int W, int Wp, int HpWp)
{
    __shared__ float tile[4][32][33];
    const int xt = blockIdx.x, y0 = blockIdx.y * 4;
    const int n  = blockIdx.z >> 3, ct = blockIdx.z & 7;
    const int tx = threadIdx.x, ty = threadIdx.y;

    const float* src = feat + (((size_t)n * CC + ct * 32 + ty) * H) * W + xt * 32 + tx;
#pragma unroll
    for (int r = 0; r < 4; r++) {
        int y = y0 + r;
        if (y < H) tile[r][ty][tx] = src[(size_t)y * W];
    }
    __syncthreads();

    const int c = ct * 32 + tx;
    const int x = xt * 32 + ty;
    __half* dst = XH + ((size_t)n * HpWp + (size_t)(y0 + 1) * Wp + (x + 1)) * CC + c;
#pragma unroll
    for (int r = 0; r < 4; r++) {
        int y = y0 + r;
        if (y < H) dst[(size_t)r * Wp * CC] = __float2half_rn(tile[r][tx][ty]);
    }
}

// ============================================================
// convM: warp-mma 3x3 conv over ALL levels, single-term fp16.
// If inH != null (layer 1): B halo filled by pure cp.async from fp16
// features. Else (layer 2): fp32 input + fused GN (interior-only) +
// fp16 convert. grid (TOTPT, 1, 32). 512 threads = 16 warps (4m x 4n).
// ============================================================
__global__ __launch_bounds__(512) void convM(
    const __half* __restrict__ inH,
    const float4* __restrict__ inC, const float4* __restrict__ inR,
    const uint4* __restrict__ WFb, int layer,
    const float* __restrict__ clscb, const float* __restrict__ regcb,
    const float* __restrict__ ssv, const float* __restrict__ shv,
    float* __restrict__ outC, float* __restrict__ outR,
    float2* __restrict__ part)
{
    extern __shared__ char smem[];
    const uint32_t sb = smem_u32(smem);

    const int bx = blockIdx.x;
    const int L = (bx >= cSegA[2]) ? 2 : (bx >= cSegA[1]) ? 1 : 0;
    const int tile = bx - cSegA[L];
    const int H = cH[L], W = cW[L], Wp = cWp[L], lgW = cLgW[L];
    const int HW = cHW[L], HpWp = cHpWp[L];
    const size_t lvlpix = (size_t)cXpix[L];

    const int tid = threadIdx.x, wid = tid >> 5, lane = tid & 31;
    const int warp_m = wid >> 2, warp_n = wid & 3;
    const int p0 = tile * 256;
    const int z = blockIdx.z;
    const int tower = z >> 4, zz = z & 15;
    const int n = zz >> 1, co0 = (zz & 1) * 128;
    const size_t nbase = lvlpix + (size_t)n * HpWp;

    const float4* in = tower ? inR : inC;
    float* Y = tower ? outR : outC;
    const uint4* WFl = WFb + (size_t)(tower * 2 + layer) * (WELEM / 8);
    const float* bias = (tower ? regcb : clscb) + layer * CC;

    const int R  = 256 >> lgW;
    const int BR = (R + 2) * Wp;
    const int prow0 = p0 >> lgW;
    const int pstart = prow0 * Wp;

    float* sS = (float*)(smem + OSS);
    float* sHh = (float*)(smem + OSH);
    if (ssv && tid < 256) {
        int so = (L * 2 + tower) * 2048 + n * 256 + tid;
        sS[tid]  = ssv[so];
        sHh[tid] = shv[so];
    }
    __syncthreads();

    float acc[2][8][4];
#pragma unroll
    for (int mt = 0; mt < 2; mt++)
#pragma unroll
        for (int nt = 0; nt < 8; nt++)
#pragma unroll
            for (int i = 0; i < 4; i++) acc[mt][nt][i] = 0.0f;

    const int lrow = lane & 7;
    const int matr = (lane >> 3) & 1;
    const int matc = lane >> 4;

    int rnp[4];
#pragma unroll
    for (int np = 0; np < 4; np++)
        rnp[np] = warp_n * 64 + np * 16 + matc * 8 + lrow;

#pragma unroll 1
    for (int kc = 0; kc < 4; kc++) {
        if (inH) {
            // ---- L1: B halo via pure cp.async from fp16 features ----
#pragma unroll 1
            for (int t = tid; t < BR * 8; t += 512) {
                int hr = t >> 3, v = t & 7;
                int gpix = pstart + hr;
                uint32_t ok = (gpix < HpWp) ? 16u : 0u;
                uint32_t d = sb + OB_H + (uint32_t)(hr * PITCH + v * 16);
                cpa16z(d, inH + (nbase + gpix) * 256 + (kc << 6) + (v << 3), ok);
            }
        } else {
            // ---- L2: fp32 -> (GN+ReLU interior-only) -> fp16 hi ----
            const int lim = BR * 16;
#pragma unroll 1
            for (int t0 = tid; t0 < lim; t0 += 2048) {
                float4 xa[4];
#pragma unroll
                for (int u = 0; u < 4; u++) {
                    int t = t0 + u * 512;
                    xa[u] = make_float4(0.f, 0.f, 0.f, 0.f);
                    if (t < lim) {
                        int hr = t >> 4, v = t & 15;
                        int gpix = pstart + hr;
                        if (gpix < HpWp)
                            xa[u] = in[(size_t)(nbase + gpix) * 64 + (kc << 4) + v];
                    }
                }
#pragma unroll
                for (int u = 0; u < 4; u++) {
                    int t = t0 + u * 512;
                    if (t >= lim) break;
                    int hr = t >> 4, v = t & 15;
                    float4 x = xa[u];
                    int hd = hr / Wp;
                    int gx = hr - hd * Wp;
                    int gy = prow0 + hd;
                    if (gy >= 1 && gy <= H && gx >= 1 && gx <= W) {
                        int c = (kc << 6) + (v << 2);
                        x.x = fmaxf(fmaf(x.x, sS[c+0], sHh[c+0]), 0.f);
                        x.y = fmaxf(fmaf(x.y, sS[c+1], sHh[c+1]), 0.f);
                        x.z = fmaxf(fmaf(x.z, sS[c+2], sHh[c+2]), 0.f);
                        x.w = fmaxf(fmaf(x.w, sS[c+3], sHh[c+3]), 0.f);
                    } else {
                        x = make_float4(0.f, 0.f, 0.f, 0.f);
                    }
                    uint32_t base = (uint32_t)(hr * PITCH + (v << 3));
                    *reinterpret_cast<uint2*>(smem + OB_H + base) =
                        make_uint2(pkh(__float2half_rn(x.x), __float2half_rn(x.y)),
                                   pkh(__float2half_rn(x.z), __float2half_rn(x.w)));
                }
            }
        }
        // ---- A tap 0 prefetch (stage 0) ----
#pragma unroll
        for (int t = tid; t < 1024; t += 512) {
            int row = t >> 3, v = t & 7;
            uint32_t d = sb + (uint32_t)(row * PITCH + v * 16);
            size_t g = (size_t)(co0 + row) * 32 + kc * 8 + v;
            cpa16(d, WFl + g);
        }
        CPA_COMMIT();
        CPA_WAIT0();
        __syncthreads();

#pragma unroll 1
        for (int tap = 0; tap < 9; tap++) {
            if (tap < 8) {
                const uint32_t abase = sb + (uint32_t)(((tap + 1) & 1) * ASTG);
#pragma unroll
                for (int t = tid; t < 1024; t += 512) {
                    int row = t >> 3, v = t & 7;
                    uint32_t d = abase + (uint32_t)(row * PITCH + v * 16);
                    size_t g = (size_t)(tap + 1) * 8192 + (size_t)(co0 + row) * 32 + kc * 8 + v;
                    cpa16(d, WFl + g);
                }
                CPA_COMMIT();
            }

            const int ky = tap / 3, kx = tap - ky * 3;
            uint32_t bOff[4];
#pragma unroll
            for (int np = 0; np < 4; np++) {
                int r = rnp[np];
                int sr = ((r >> lgW) + ky) * Wp + (r & (W - 1)) + kx;
                bOff[np] = (uint32_t)(sr * PITCH);
            }
            const uint32_t sAH = sb + (uint32_t)((tap & 1) * ASTG);
            const uint32_t sBH = sb + OB_H;
            const int m0 = warp_m * 32;

#pragma unroll
            for (int ks = 0; ks < 4; ks++) {
                uint32_t ah[2][4], bb[4][4];
#pragma unroll
                for (int mt = 0; mt < 2; mt++) {
                    uint32_t off = (uint32_t)((m0 + mt * 16 + matr * 8 + lrow) * PITCH
                                              + (ks * 16 + matc * 8) * 2);
                    ldsm_x4(ah[mt][0], ah[mt][1], ah[mt][2], ah[mt][3], sAH + off);
                }
                const uint32_t kb = (uint32_t)((ks * 16 + matr * 8) * 2);
#pragma unroll
                for (int np = 0; np < 4; np++)
                    ldsm_x4(bb[np][0], bb[np][1], bb[np][2], bb[np][3],
                            sBH + bOff[np] + kb);
#pragma unroll
                for (int mt = 0; mt < 2; mt++)
#pragma unroll
                    for (int np = 0; np < 4; np++) {
                        mma_f16(acc[mt][np * 2 + 0], ah[mt], &bb[np][0]);
                        mma_f16(acc[mt][np * 2 + 1], ah[mt], &bb[np][2]);
                    }
            }
            if (tap < 8) CPA_WAIT0();
            __syncthreads();
        }
    }

    // ---- epilogue: bias, store fp32 padded NHWC, deterministic GN partials ----
    __shared__ float redS[16][2], redQ[16][2];
    const int qrow = lane >> 2, qcol = (lane & 3) * 2;
    float sg[2] = {0.0f, 0.0f}, qg[2] = {0.0f, 0.0f};

#pragma unroll
    for (int mt = 0; mt < 2; mt++) {
#pragma unroll
        for (int h8 = 0; h8 < 2; h8++) {
            const int col_ = co0 + warp_m * 32 + mt * 16 + qrow + h8 * 8;
            const float b = bias[col_];
#pragma unroll
            for (int nt = 0; nt < 8; nt++) {
#pragma unroll
                for (int cc2 = 0; cc2 < 2; cc2++) {
                    int p = p0 + warp_n * 64 + nt * 8 + qcol + cc2;
                    float v = acc[mt][nt][h8 * 2 + cc2] + b;
                    if (p < HW) {
                        int x = p & (W - 1), y = p >> lgW;
                        Y[(nbase + (size_t)(y + 1) * Wp + (x + 1)) * CC + col_] = v;
                        sg[mt] += v;
                        qg[mt] += v * v;
                    }
                }
            }
        }
    }
#pragma unroll
    for (int off = 16; off > 0; off >>= 1) {
#pragma unroll
        for (int mt = 0; mt < 2; mt++) {
            sg[mt] += __shfl_down_sync(0xffffffffu, sg[mt], off);
            qg[mt] += __shfl_down_sync(0xffffffffu, qg[mt], off);
        }
    }
    if (lane == 0) {
        redS[wid][0] = sg[0]; redS[wid][1] = sg[1];
        redQ[wid][0] = qg[0]; redQ[wid][1] = qg[1];
    }
    __syncthreads();
    if (tid < 8) {
        int wm = tid >> 1, mt = tid & 1;
        float S = 0.0f, Q = 0.0f;
#pragma unroll
        for (int wn = 0; wn < 4; wn++) {
            S += redS[wm * 4 + wn][mt];
            Q += redQ[wm * 4 + wn][mt];
        }
        size_t pidx = (size_t)z * TOTPT + bx;
        part[pidx * 8 + tid] = make_float2(S, Q);
    }
}

// ============================================================
// gn_finalize2: 768 blocks = (level, tower, n, group), all levels.
// ============================================================
__global__ __launch_bounds__(256) void gn_finalize2(
    const float2* __restrict__ part,
    const float* __restrict__ clsg, const float* __restrict__ clsbt,
    const float* __restrict__ regg, const float* __restrict__ regbt,
    float* __restrict__ oss, float* __restrict__ osh)
{
    const int b = blockIdx.x;
    const int L = b >> 8;
    const int r = b & 255;
    const int tower = r >> 7;
    const int rr = r & 127;
    const int n = rr >> 4, grp = rr & 15;
    const int half = grp >> 3, i = grp & 7;
    const int z = tower * 16 + n * 2 + half;
    const int seg = cSegA[L], PT = cPT[L];

    float S = 0.0f, Q = 0.0f;
    for (int t = threadIdx.x; t < PT; t += 256) {
        float2 p = part[(size_t)(z * TOTPT + seg + t) * 8 + i];
        S += p.x; Q += p.y;
    }
    __shared__ float sS[256], sQ[256];
    sS[threadIdx.x] = S; sQ[threadIdx.x] = Q;
    __syncthreads();
    for (int off = 128; off > 0; off >>= 1) {
        if (threadIdx.x < off) {
            sS[threadIdx.x] += sS[threadIdx.x + off];
            sQ[threadIdx.x] += sQ[threadIdx.x + off];
        }
        __syncthreads();
    }
    if (threadIdx.x < 16) {
        float cnt  = (float)(GSIZE * cHW[L]);
        float mean = sS[0] / cnt;
        float var  = sQ[0] / cnt - mean * mean;
        float rstd = rsqrtf(var + GN_EPS);
        int c = grp * 16 + threadIdx.x;
        float gam = tower ? regg[c] : clsg[c];
        float bet = tower ? regbt[c] : clsbt[c];
        float scale = rstd * gam;
        int so = (L * 2 + tower) * 2048 + n * 256 + c;
        oss[so] = scale;
        osh[so] = bet - mean * scale;
    }
}

// ============================================================
// convO: head convs over ALL levels, SINGLE-TERM (act hi only).
// grid (TOTPT, 1, 16): z = n*2 + mode. 256 threads = 8 warps.
// ============================================================
__global__ __launch_bounds__(256) void convO(
    const float4* __restrict__ inC, const float4* __restrict__ inR,
    const uint4* __restrict__ WOFb,
    const float* __restrict__ ssv, const float* __restrict__ shv,
    const float* __restrict__ clsb, const float* __restrict__ regb,
    const float* __restrict__ ctrb, float* __restrict__ out)
{
    extern __shared__ char smem[];
    const uint32_t sb = smem_u32(smem);

    const int bx = blockIdx.x;
    const int L = (bx >= cSegA[2]) ? 2 : (bx >= cSegA[1]) ? 1 : 0;
    const int tile = bx - cSegA[L];
    const int H = cH[L], W = cW[L], Wp = cWp[L], lgW = cLgW[L];
    const int HW = cHW[L], HpWp = cHpWp[L];
    const int poff = cPoff[L];
    const size_t lvlpix = (size_t)cXpix[L];

    const int tid = threadIdx.x, wid = tid >> 5, lane = tid & 31;
    const int p0 = tile * 256;
    const int z = blockIdx.z;
    const int n = z >> 1, mode = z & 1;
    const size_t nbase = lvlpix + (size_t)n * HpWp;

    const float4* in = mode ? inR : inC;
    const uint4* WFl = WOFb + (size_t)mode * (WOELEM / 8);

    const int R  = 256 >> lgW;
    const int BR = (R + 2) * Wp;
    const int prow0 = p0 >> lgW;
    const int pstart = prow0 * Wp;

    float* sS = (float*)(smem + OSS_O);
    float* sHh = (float*)(smem + OSH_O);
    if (tid < 256) {
        int so = (L * 2 + mode) * 2048 + n * 256 + tid;
        sS[tid]  = ssv[so];
        sHh[tid] = shv[so];
    }
    __syncthreads();

    float acc[2][4][4];
#pragma unroll
    for (int mt = 0; mt < 2; mt++)
#pragma unroll
        for (int nt = 0; nt < 4; nt++)
#pragma unroll
            for (int i = 0; i < 4; i++) acc[mt][nt][i] = 0.0f;

    const int lrow = lane & 7;
    const int matr = (lane >> 3) & 1;
    const int matc = lane >> 4;

    int rnp[2];
#pragma unroll
    for (int np = 0; np < 2; np++)
        rnp[np] = wid * 32 + np * 16 + matc * 8 + lrow;

#pragma unroll 1
    for (int kc = 0; kc < 4; kc++) {
        // ---- B halo fill (fp32 + interior-only GN + fp16 hi) ----
        {
            const int lim = BR * 16;
#pragma unroll 1
            for (int t0 = tid; t0 < lim; t0 += 1024) {
                float4 xa[4];
#pragma unroll
                for (int u = 0; u < 4; u++) {
                    int t = t0 + u * 256;
                    xa[u] = make_float4(0.f, 0.f, 0.f, 0.f);
                    if (t < lim) {
                        int hr = t >> 4, v = t & 15;
                        int gpix = pstart + hr;
                        if (gpix < HpWp)
                            xa[u] = in[(size_t)(nbase + gpix) * 64 + (kc << 4) + v];
                    }
                }
#pragma unroll
                for (int u = 0; u < 4; u++) {
                    int t = t0 + u * 256;
                    if (t >= lim) break;
                    int hr = t >> 4, v = t & 15;
                    float4 x = xa[u];
                    int hd = hr / Wp;
                    int gx = hr - hd * Wp;
                    int gy = prow0 + hd;
                    if (gy >= 1 && gy <= H && gx >= 1 && gx <= W) {
                        int c = (kc << 6) + (v << 2);
                        x.x = fmaxf(fmaf(x.x, sS[c+0], sHh[c+0]), 0.f);
                        x.y = fmaxf(fmaf(x.y, sS[c+1], sHh[c+1]), 0.f);
                        x.z = fmaxf(fmaf(x.z, sS[c+2], sHh[c+2]), 0.f);
                        x.w = fmaxf(fmaf(x.w, sS[c+3], sHh[c+3]), 0.f);
                    } else {
                        x = make_float4(0.f, 0.f, 0.f, 0.f);
                    }
                    uint32_t base = (uint32_t)(hr * PITCH + (v << 3));
                    *reinterpret_cast<uint2*>(smem + OB_H_O + base) =
                        make_uint2(pkh(__float2half_rn(x.x), __float2half_rn(x.y)),
                                   pkh(__float2half_rn(x.z), __float2half_rn(x.w)));
                }
            }
        }
        // ---- A tap 0 prefetch ----
        {
            int row = tid >> 3, v = tid & 7;
            uint32_t d = sb + (uint32_t)(row * PITCH + v * 16);
            size_t g = (size_t)row * 32 + kc * 8 + v;
            cpa16(d, WFl + g);
        }
        CPA_COMMIT();
        CPA_WAIT0();
        __syncthreads();

#pragma unroll 1
        for (int tap = 0; tap < 9; tap++) {
            if (tap < 8) {
                const uint32_t abase = sb + (uint32_t)(((tap + 1) & 1) * ASTG_O);
                int row = tid >> 3, v = tid & 7;
                uint32_t d = abase + (uint32_t)(row * PITCH + v * 16);
                size_t g = (size_t)(tap + 1) * 1024 + (size_t)row * 32 + kc * 8 + v;
                cpa16(d, WFl + g);
                CPA_COMMIT();
            }

            const int ky = tap / 3, kx = tap - ky * 3;
            uint32_t bOff[2];
#pragma unroll
            for (int np = 0; np < 2; np++) {
                int r = rnp[np];
                int sr = ((r >> lgW) + ky) * Wp + (r & (W - 1)) + kx;
                bOff[np] = (uint32_t)(sr * PITCH);
            }
            const uint32_t sAH = sb + (uint32_t)((tap & 1) * ASTG_O);
            const uint32_t sBH = sb + OB_H_O;

#pragma unroll
            for (int ks = 0; ks < 4; ks++) {
                uint32_t ah[2][4], bb[2][4];
#pragma unroll
                for (int mt = 0; mt < 2; mt++) {
                    uint32_t off = (uint32_t)((mt * 16 + matr * 8 + lrow) * PITCH
                                              + (ks * 16 + matc * 8) * 2);
                    ldsm_x4(ah[mt][0], ah[mt][1], ah[mt][2], ah[mt][3], sAH + off);
                }
                const uint32_t kb = (uint32_t)((ks * 16 + matr * 8) * 2);
#pragma unroll
                for (int np = 0; np < 2; np++)
                    ldsm_x4(bb[np][0], bb[np][1], bb[np][2], bb[np][3],
                            sBH + bOff[np] + kb);
#pragma unroll
                for (int mt = 0; mt < 2; mt++)
#pragma unroll
                    for (int np = 0; np < 2; np++) {
                        mma_f16(acc[mt][np * 2 + 0], ah[mt], &bb[np][0]);
                        mma_f16(acc[mt][np * 2 + 1], ah[mt], &bb[np][2]);
                    }
            }
            if (tap < 8) CPA_WAIT0();
            __syncthreads();
        }
    }

    // ---- epilogue: scatter into concat output layout ----
    const int qrow = lane >> 2, qcol = (lane & 3) * 2;
#pragma unroll
    for (int mt = 0; mt < 2; mt++) {
#pragma unroll
        for (int h8 = 0; h8 < 2; h8++) {
            const int row = mt * 16 + h8 * 8 + qrow;
#pragma unroll
            for (int nt = 0; nt < 4; nt++) {
#pragma unroll
                for (int cc2 = 0; cc2 < 2; cc2++) {
                    int p = p0 + wid * 32 + nt * 8 + qcol + cc2;
                    if (p >= HW) continue;
                    float v = acc[mt][nt][h8 * 2 + cc2];
                    int x = p & (W - 1), y = p >> lgW;
                    size_t gp = (size_t)n * TOTHW + poff + (size_t)y * W + x;
                    if (mode == 0) {
                        if (row < 20) out[CLSBASE + gp * 20 + row] = v + clsb[row];
                    } else {
                        if (row < 4)
                            out[REGBASE + gp * 4 + row] = fmaxf(v + regb[row], 0.0f);
                        else if (row == 4)
                            out[CTRBASE + gp] = v + ctrb[0];
                    }
                }
            }
        }
    }
}

// ============================================================
// host launcher
// ============================================================
extern "C" void kernel_launch(void* const* d_in, const int* in_sizes, int n_in,
                              void* d_out, int out_size)
{
    (void)in_sizes; (void)n_in; (void)out_size;

    const float* feat[3] = { (const float*)d_in[0], (const float*)d_in[1],
                             (const float*)d_in[2] };
    const float* cls_conv_w = (const float*)d_in[3];
    const float* cls_conv_b = (const float*)d_in[4];
    const float* cls_gn_g   = (const float*)d_in[5];
    const float* cls_gn_b   = (const float*)d_in[6];
    const float* cls_out_w  = (const float*)d_in[7];
    const float* cls_out_b  = (const float*)d_in[8];
    const float* reg_conv_w = (const float*)d_in[9];
    const float* reg_conv_b = (const float*)d_in[10];
    const float* reg_gn_g   = (const float*)d_in[11];
    const float* reg_gn_b   = (const float*)d_in[12];
    const float* reg_out_w  = (const float*)d_in[13];
    const float* reg_out_b  = (const float*)d_in[14];
    const float* ctr_w      = (const float*)d_in[15];
    const float* ctr_b      = (const float*)d_in[16];

    float* out = (float*)d_out;

    __half *XFH, *WF, *WOF;
    float *Y0, *Y1, *Y2, *Y3, *ssv, *shv;
    float2* part;
    cudaGetSymbolAddress((void**)&XFH, g_XFH);
    {
        float* ybase;
        cudaGetSymbolAddress((void**)&ybase, g_Y);
        Y0 = ybase;
        Y1 = ybase + (size_t)XCAP2;
        Y2 = ybase + 2 * (size_t)XCAP2;
        Y3 = ybase + 3 * (size_t)XCAP2;
    }
    cudaGetSymbolAddress((void**)&WF, g_WF);
    cudaGetSymbolAddress((void**)&WOF, g_WOF);
    cudaGetSymbolAddress((void**)&ssv, g_ssv);
    cudaGetSymbolAddress((void**)&shv, g_shv);
    cudaGetSymbolAddress((void**)&part, g_part);

    cudaFuncSetAttribute(convM, cudaFuncAttributeMaxDynamicSharedMemorySize, CM_DYN);
    cudaFuncSetAttribute(convO, cudaFuncAttributeMaxDynamicSharedMemorySize, CO_DYN);

    wprep<<<(4 * WELEM + 255) / 256, 256>>>(cls_conv_w, reg_conv_w, WF);
    woprep<<<(2 * WOELEM + 255) / 256, 256>>>(cls_out_w, reg_out_w, ctr_w, WOF);

    const int hH[3] = {100, 50, 25};
    const int hW[3] = {128, 64, 32};
    const int hWp[3] = {130, 66, 34};
    const int hHpWp[3] = {13260, 3432, 918};
    const size_t hXoff[3] = {0, 106080ull * 256, 133536ull * 256};

    for (int L = 0; L < 3; L++) {
        const int H = hH[L], W = hW[L], Wp = hWp[L], HpWp = hHpWp[L];
        const int zpN = (NB * (2 * Wp + 2 * H) * 32 + 255) / 256;
        zeropad_h<<<zpN, 256>>>((uint4*)(XFH + hXoff[L]), H, W, Wp, HpWp);
        dim3 fgrid(W / 32, (H + 3) / 4, NB * 8);
        featprep4<<<fgrid, dim3(32, 32)>>>(feat[L], XFH + hXoff[L], H, W, Wp, HpWp);
    }

    dim3 cgrid(TOTPT, 1, 32);
    dim3 ogrid(TOTPT, 1, 16);

    // conv layer 1: fp16 feature input, pure cp.async B fill
    convM<<<cgrid, 512, CM_DYN>>>(
        XFH, nullptr, nullptr,
        (const uint4*)WF, 0,
        cls_conv_b, reg_conv_b, nullptr, nullptr,
        Y0, Y1, part);
    gn_finalize2<<<768, 256>>>(part,
        cls_gn_g, cls_gn_b, reg_gn_g, reg_gn_b, ssv, shv);

    // conv layer 2: fp32 Y input, GN fused on load
    convM<<<cgrid, 512, CM_DYN>>>(
        nullptr, (const float4*)Y0, (const float4*)Y1,
        (const uint4*)WF, 1,
        cls_conv_b, reg_conv_b, ssv, shv,
        Y2, Y3, part);
    gn_finalize2<<<768, 256>>>(part,
        cls_gn_g + CC, cls_gn_b + CC, reg_gn_g + CC, reg_gn_b + CC,
        ssv + 12288, shv + 12288);

    // heads (single-term), GN of layer 2 fused on load
    convO<<<ogrid, 256, CO_DYN>>>(
        (const float4*)Y2, (const float4*)Y3,
        (const uint4*)WOF,
        ssv + 12288, shv + 12288,
        cls_out_b, reg_out_b, ctr_b, out);
}